// round 1
// baseline (speedup 1.0000x reference)
#include <cuda_runtime.h>

#define Dn 1024
#define Bn 16
#define Rn 100

// Scratch (device globals; no allocations allowed)
__device__ float g_Wsum[Dn * Dn];   // mean_r gate_W[r,k,j]  (k-major, j contig)
__device__ float g_mb[Dn];          // mean_r gate_b[r,k]
__device__ float g_Ccos[Dn * Dn];   // cos(phase)[i,m]
__device__ float g_ET[Dn * Dn];     // E^T  [j,n]
__device__ float g_M[Dn * Dn];      // M = QW @ E     [m,j]
__device__ float g_G[Dn * Dn];      // G = M @ Wsum^T [m,k]
__device__ float g_GT[Dn * Dn];     // G^T            [k,m]

// ---------------------------------------------------------------------------
// Reduction of gate_W over R: Wsum[k,j] = (1/R) sum_r gate_W[r,k,j]
// Streams 400MB; fully coalesced (all threads scan the same r-slab together).
// ---------------------------------------------------------------------------
__global__ void reduce_w_kernel(const float* __restrict__ gw) {
    int i4 = blockIdx.x * blockDim.x + threadIdx.x;   // 0 .. D*D/4-1
    const float4* p = reinterpret_cast<const float4*>(gw);
    float ax = 0.f, ay = 0.f, az = 0.f, aw = 0.f;
    #pragma unroll 4
    for (int r = 0; r < Rn; ++r) {
        float4 v = p[(size_t)r * (Dn * Dn / 4) + i4];
        ax += v.x; ay += v.y; az += v.z; aw += v.w;
    }
    const float inv = 1.0f / (float)Rn;
    float4 o; o.x = ax * inv; o.y = ay * inv; o.z = az * inv; o.w = aw * inv;
    reinterpret_cast<float4*>(g_Wsum)[i4] = o;
}

__global__ void reduce_b_kernel(const float* __restrict__ gb) {
    int k = blockIdx.x * blockDim.x + threadIdx.x;    // 0..1023
    float acc = 0.f;
    #pragma unroll 4
    for (int r = 0; r < Rn; ++r) acc += gb[r * Dn + k];
    g_mb[k] = acc / (float)Rn;
}

__global__ void cos_kernel(const float* __restrict__ ph) {
    int i = blockIdx.x * blockDim.x + threadIdx.x;
    g_Ccos[i] = cosf(ph[i]);
}

// ---------------------------------------------------------------------------
// 32x32 tiled transpose
// ---------------------------------------------------------------------------
__device__ __forceinline__ void transpose_body(const float* __restrict__ in,
                                               float* __restrict__ out) {
    __shared__ float tile[32][33];
    int x = blockIdx.x * 32 + threadIdx.x;
    int y = blockIdx.y * 32 + threadIdx.y;
    #pragma unroll
    for (int j = 0; j < 32; j += 8)
        tile[threadIdx.y + j][threadIdx.x] = in[(y + j) * Dn + x];
    __syncthreads();
    x = blockIdx.y * 32 + threadIdx.x;
    y = blockIdx.x * 32 + threadIdx.y;
    #pragma unroll
    for (int j = 0; j < 32; j += 8)
        out[(y + j) * Dn + x] = tile[threadIdx.x][threadIdx.y + j];
}

__global__ void transpose_E_kernel(const float* __restrict__ E) { transpose_body(E, g_ET); }
__global__ void transpose_G_kernel()                             { transpose_body(g_G, g_GT); }

// ---------------------------------------------------------------------------
// Dot-form GEMM: C[i,n] = sum_k A[i,k] * B[n,k]   (both operands k-contiguous)
// ---------------------------------------------------------------------------
template <int BM, int BN, int BK, int TM, int TN>
__device__ __forceinline__ void gemm_dot_body(const float* __restrict__ A,
                                              const float* __restrict__ B,
                                              float* __restrict__ C) {
    constexpr int THREADS = (BM / TM) * (BN / TN);
    constexpr int PADM = BM + 4;
    constexpr int PADN = BN + 4;
    constexpr int KV4 = BK / 4;
    constexpr int LOADS_A = (BM * BK / 4) / THREADS;
    constexpr int LOADS_B = (BN * BK / 4) / THREADS;

    __shared__ float As[BK][PADM];
    __shared__ float Bs[BK][PADN];

    const int i0 = blockIdx.y * BM;
    const int n0 = blockIdx.x * BN;
    const int tid = threadIdx.x;
    const int tr = tid / (BN / TN);
    const int tc = tid % (BN / TN);

    float acc[TM][TN];
    #pragma unroll
    for (int a = 0; a < TM; ++a)
        #pragma unroll
        for (int b = 0; b < TN; ++b) acc[a][b] = 0.f;

    for (int k0 = 0; k0 < Dn; k0 += BK) {
        #pragma unroll
        for (int l = 0; l < LOADS_A; ++l) {
            int idx = tid + l * THREADS;
            int row = idx / KV4, c4 = idx % KV4;
            float4 v = *reinterpret_cast<const float4*>(A + (size_t)(i0 + row) * Dn + k0 + c4 * 4);
            As[c4 * 4 + 0][row] = v.x; As[c4 * 4 + 1][row] = v.y;
            As[c4 * 4 + 2][row] = v.z; As[c4 * 4 + 3][row] = v.w;
        }
        #pragma unroll
        for (int l = 0; l < LOADS_B; ++l) {
            int idx = tid + l * THREADS;
            int row = idx / KV4, c4 = idx % KV4;
            float4 v = *reinterpret_cast<const float4*>(B + (size_t)(n0 + row) * Dn + k0 + c4 * 4);
            Bs[c4 * 4 + 0][row] = v.x; Bs[c4 * 4 + 1][row] = v.y;
            Bs[c4 * 4 + 2][row] = v.z; Bs[c4 * 4 + 3][row] = v.w;
        }
        __syncthreads();

        #pragma unroll
        for (int kk = 0; kk < BK; ++kk) {
            float ar[TM], br[TN];
            #pragma unroll
            for (int t = 0; t < TM / 4; ++t) {
                float4 v = *reinterpret_cast<const float4*>(&As[kk][tr * TM + t * 4]);
                ar[t * 4 + 0] = v.x; ar[t * 4 + 1] = v.y; ar[t * 4 + 2] = v.z; ar[t * 4 + 3] = v.w;
            }
            #pragma unroll
            for (int t = 0; t < TN / 4; ++t) {
                float4 v = *reinterpret_cast<const float4*>(&Bs[kk][tc * TN + t * 4]);
                br[t * 4 + 0] = v.x; br[t * 4 + 1] = v.y; br[t * 4 + 2] = v.z; br[t * 4 + 3] = v.w;
            }
            #pragma unroll
            for (int a = 0; a < TM; ++a)
                #pragma unroll
                for (int b = 0; b < TN; ++b) acc[a][b] += ar[a] * br[b];
        }
        __syncthreads();
    }

    #pragma unroll
    for (int a = 0; a < TM; ++a) {
        int row = i0 + tr * TM + a;
        #pragma unroll
        for (int b = 0; b < TN; b += 4) {
            float4 v; v.x = acc[a][b]; v.y = acc[a][b + 1]; v.z = acc[a][b + 2]; v.w = acc[a][b + 3];
            *reinterpret_cast<float4*>(C + (size_t)row * Dn + n0 + tc * TN + b) = v;
        }
    }
}

// M[m,j] = sum_n QW[m,n] * ET[j,n]
__global__ void gemm_M_kernel(const float* __restrict__ qw) {
    gemm_dot_body<64, 64, 16, 4, 4>(qw, g_ET, g_M);
}
// G[m,k] = sum_j M[m,j] * Wsum[k,j]
__global__ void gemm_G_kernel() {
    gemm_dot_body<64, 64, 16, 4, 4>(g_M, g_Wsum, g_G);
}

// ---------------------------------------------------------------------------
// Final GEMM: out[b,i,k] = sum_m (Ccos[i,m] * x[b,m]) * GT[k,m] + mb[k]
// blockIdx = (k_tile, i_tile, b); 128x128 tile, 8x8 per thread, BK=16.
// ---------------------------------------------------------------------------
__global__ void gemm_final_kernel(const float* __restrict__ x,
                                  float* __restrict__ out) {
    constexpr int BM = 128, BN = 128, BK = 16, TM = 8, TN = 8;
    constexpr int THREADS = 256;
    constexpr int PAD = BM + 4;
    constexpr int KV4 = BK / 4;

    __shared__ float As[BK][PAD];
    __shared__ float Bs[BK][PAD];

    const int b  = blockIdx.z;
    const int i0 = blockIdx.y * BM;
    const int n0 = blockIdx.x * BN;   // k (output column) tile
    const float* __restrict__ xb = x + (size_t)b * Dn;

    const int tid = threadIdx.x;
    const int tr = tid / (BN / TN);
    const int tc = tid % (BN / TN);

    float acc[TM][TN];
    #pragma unroll
    for (int a = 0; a < TM; ++a)
        #pragma unroll
        for (int c = 0; c < TN; ++c) acc[a][c] = 0.f;

    for (int k0 = 0; k0 < Dn; k0 += BK) {
        #pragma unroll
        for (int l = 0; l < 2; ++l) {
            int idx = tid + l * THREADS;
            int row = idx / KV4, c4 = idx % KV4;
            float4 v  = *reinterpret_cast<const float4*>(g_Ccos + (size_t)(i0 + row) * Dn + k0 + c4 * 4);
            float4 xs = *reinterpret_cast<const float4*>(xb + k0 + c4 * 4);
            As[c4 * 4 + 0][row] = v.x * xs.x; As[c4 * 4 + 1][row] = v.y * xs.y;
            As[c4 * 4 + 2][row] = v.z * xs.z; As[c4 * 4 + 3][row] = v.w * xs.w;
        }
        #pragma unroll
        for (int l = 0; l < 2; ++l) {
            int idx = tid + l * THREADS;
            int row = idx / KV4, c4 = idx % KV4;
            float4 v = *reinterpret_cast<const float4*>(g_GT + (size_t)(n0 + row) * Dn + k0 + c4 * 4);
            Bs[c4 * 4 + 0][row] = v.x; Bs[c4 * 4 + 1][row] = v.y;
            Bs[c4 * 4 + 2][row] = v.z; Bs[c4 * 4 + 3][row] = v.w;
        }
        __syncthreads();

        #pragma unroll
        for (int kk = 0; kk < BK; ++kk) {
            float ar[TM], br[TN];
            #pragma unroll
            for (int t = 0; t < TM / 4; ++t) {
                float4 v = *reinterpret_cast<const float4*>(&As[kk][tr * TM + t * 4]);
                ar[t * 4 + 0] = v.x; ar[t * 4 + 1] = v.y; ar[t * 4 + 2] = v.z; ar[t * 4 + 3] = v.w;
            }
            #pragma unroll
            for (int t = 0; t < TN / 4; ++t) {
                float4 v = *reinterpret_cast<const float4*>(&Bs[kk][tc * TN + t * 4]);
                br[t * 4 + 0] = v.x; br[t * 4 + 1] = v.y; br[t * 4 + 2] = v.z; br[t * 4 + 3] = v.w;
            }
            #pragma unroll
            for (int a = 0; a < TM; ++a)
                #pragma unroll
                for (int c = 0; c < TN; ++c) acc[a][c] += ar[a] * br[c];
        }
        __syncthreads();
    }

    float* __restrict__ outb = out + (size_t)b * Dn * Dn;
    #pragma unroll
    for (int a = 0; a < TM; ++a) {
        int row = i0 + tr * TM + a;
        #pragma unroll
        for (int c = 0; c < TN; c += 4) {
            int col = n0 + tc * TN + c;
            float4 mbv = *reinterpret_cast<const float4*>(&g_mb[col]);
            float4 v;
            v.x = acc[a][c + 0] + mbv.x;
            v.y = acc[a][c + 1] + mbv.y;
            v.z = acc[a][c + 2] + mbv.z;
            v.w = acc[a][c + 3] + mbv.w;
            *reinterpret_cast<float4*>(outb + (size_t)row * Dn + col) = v;
        }
    }
}

// ---------------------------------------------------------------------------
// kernel_launch
// Inputs (metadata order): x(16,1,1024), quantum_weights(1024,1024),
// quantum_phase(1024,1024), entanglement_matrix(1024,1024),
// gate_W(100,1024,1024), gate_b(100,1024). Output: (16,1024,1024) fp32.
// ---------------------------------------------------------------------------
extern "C" void kernel_launch(void* const* d_in, const int* in_sizes, int n_in,
                              void* d_out, int out_size) {
    const float* x  = (const float*)d_in[0];
    const float* qw = (const float*)d_in[1];
    const float* ph = (const float*)d_in[2];
    const float* em = (const float*)d_in[3];
    const float* gw = (const float*)d_in[4];
    const float* gb = (const float*)d_in[5];
    float* out = (float*)d_out;

    // Independent precomputes
    reduce_w_kernel<<<(Dn * Dn / 4) / 256, 256>>>(gw);
    reduce_b_kernel<<<Dn / 256, 256>>>(gb);
    cos_kernel<<<(Dn * Dn) / 256, 256>>>(ph);
    transpose_E_kernel<<<dim3(Dn / 32, Dn / 32), dim3(32, 8)>>>(em);

    // M = QW @ E  (dot form against E^T)
    gemm_M_kernel<<<dim3(Dn / 64, Dn / 64), 256>>>(qw);
    // G = M @ Wsum^T
    gemm_G_kernel<<<dim3(Dn / 64, Dn / 64), 256>>>();
    // G^T for dot-form final GEMM
    transpose_G_kernel<<<dim3(Dn / 32, Dn / 32), dim3(32, 8)>>>();

    // out[b,i,k] = sum_m (cos(phase)[i,m]*x[b,m]) * GT[k,m] + mb[k]
    gemm_final_kernel<<<dim3(Dn / 128, Dn / 128, Bn), 256>>>(x, out);
}